// round 9
// baseline (speedup 1.0000x reference)
#include <cuda_runtime.h>
#include <cuda_fp16.h>
#include <math.h>

#define L_TOK 32768

// ---------------- scratch (device globals; no runtime allocation) ----------------
__device__ float  g_x  [L_TOK * 256];   // residual stream (fp32)
__device__ __half g_win[L_TOK * 256];   // LN output / partitioned windows (fp16)
__device__ __half g_qkv[L_TOK * 768];   // qkv (fp16)
__device__ __half g_att[L_TOK * 256];   // attention out (fp16, window layout)
__device__ __half g_mlp[L_TOK * 1024];  // MLP hidden (fp16)
__device__ __half g_wbuf[2 * 786432];   // fp16 weights

__device__ __forceinline__ int win_to_tok(int r, int shift) {
    int w = r >> 6, n = r & 63;
    int h  = ((w >> 6) << 2)        + (n >> 4);
    int wy = (((w >> 3) & 7) << 2)  + ((n >> 2) & 3);
    int t  = ((w & 7) << 2)         + (n & 3);
    h  = (h  + shift) & 31;
    wy = (wy + shift) & 31;
    t  = (t  + shift) & 31;
    return (h << 10) + (wy << 5) + t;
}

__device__ __forceinline__ void cp16(void* s, const void* g) {
    unsigned sa = (unsigned)__cvta_generic_to_shared(s);
    asm volatile("cp.async.cg.shared.global [%0], [%1], 16;\n" :: "r"(sa), "l"(g));
}
__device__ __forceinline__ unsigned smem_u32(const void* p) {
    unsigned a;
    asm("{ .reg .u64 t; cvta.to.shared.u64 t, %1; cvt.u32.u64 %0, t; }" : "=r"(a) : "l"(p));
    return a;
}
__device__ __forceinline__ void mma_f16(float* d, const unsigned* a, const unsigned* b) {
    asm volatile(
        "mma.sync.aligned.m16n8k16.row.col.f32.f16.f16.f32 "
        "{%0,%1,%2,%3}, {%4,%5,%6,%7}, {%8,%9}, {%0,%1,%2,%3};\n"
        : "+f"(d[0]), "+f"(d[1]), "+f"(d[2]), "+f"(d[3])
        : "r"(a[0]), "r"(a[1]), "r"(a[2]), "r"(a[3]), "r"(b[0]), "r"(b[1]));
}
__device__ __forceinline__ void ldsm4(unsigned* r, unsigned addr) {
    asm volatile("ldmatrix.sync.aligned.m8n8.x4.shared.b16 {%0,%1,%2,%3}, [%4];"
        : "=r"(r[0]), "=r"(r[1]), "=r"(r[2]), "=r"(r[3]) : "r"(addr));
}
__device__ __forceinline__ void ldsm2(unsigned* r, unsigned addr) {
    asm volatile("ldmatrix.sync.aligned.m8n8.x2.shared.b16 {%0,%1}, [%2];"
        : "=r"(r[0]), "=r"(r[1]) : "r"(addr));
}
__device__ __forceinline__ unsigned packh2(float a, float b) {
    __half2 h = __floats2half2_rn(a, b);
    return *(unsigned*)&h;
}

// ---------------- residual init ----------------
__global__ void k_copy(const float* __restrict__ src) {
    int i = blockIdx.x * 256 + threadIdx.x;
    ((float4*)g_x)[i] = ((const float4*)src)[i];
}

// ---------------- fp16 weight conversion (all 8 weight tensors, one launch) ----------------
__global__ void k_roundall(const float* s0, const float* s1, const float* s2, const float* s3,
                           const float* s4, const float* s5, const float* s6, const float* s7) {
    int i = blockIdx.x * 256 + threadIdx.x;            // 0 .. 393215 (float4 units)
    int set = i >= 196608;
    int j = set ? i - 196608 : i;
    const float* src;
    int dstoff;
    if      (j <  49152) { src = set ? s4 : s0; dstoff = j; }
    else if (j <  65536) { src = set ? s5 : s1; dstoff = (196608 >> 2) + (j - 49152); }
    else if (j < 131072) { src = set ? s6 : s2; dstoff = (262144 >> 2) + (j - 65536); }
    else                 { src = set ? s7 : s3; dstoff = (524288 >> 2) + (j - 131072); }
    int local = (j < 49152) ? j : (j < 65536) ? j - 49152 : (j < 131072) ? j - 65536 : j - 131072;
    float4 v = ((const float4*)src)[local];
    uint2 o;
    o.x = packh2(v.x, v.y);
    o.y = packh2(v.z, v.w);
    ((uint2*)(g_wbuf + set * 786432))[dstoff] = o;
}

// ---------------- LayerNorm (REMAP=1: fused shift+partition gather); fp16 out ----------------
template<int REMAP>
__global__ __launch_bounds__(256) void k_ln(const float* __restrict__ gam,
                                            const float* __restrict__ bet, int shift) {
    int warp = threadIdx.x >> 5, lane = threadIdx.x & 31;
    int r = (blockIdx.x << 3) + warp;
    int src = REMAP ? win_to_tok(r, shift) : r;
    const float4* xp = (const float4*)(g_x + src * 256);
    float4 a = xp[lane * 2], c = xp[lane * 2 + 1];
    float s  = a.x + a.y + a.z + a.w + c.x + c.y + c.z + c.w;
    float sq = a.x*a.x + a.y*a.y + a.z*a.z + a.w*a.w
             + c.x*c.x + c.y*c.y + c.z*c.z + c.w*c.w;
    #pragma unroll
    for (int o = 16; o; o >>= 1) {
        s  += __shfl_xor_sync(0xffffffffu, s, o);
        sq += __shfl_xor_sync(0xffffffffu, sq, o);
    }
    float mean = s * (1.0f / 256.0f);
    float inv = rsqrtf(sq * (1.0f / 256.0f) - mean * mean + 1e-5f);
    float4 g0 = ((const float4*)gam)[lane*2], g1 = ((const float4*)gam)[lane*2+1];
    float4 b0 = ((const float4*)bet)[lane*2], b1 = ((const float4*)bet)[lane*2+1];
    uint4 o;
    o.x = packh2((a.x-mean)*inv*g0.x + b0.x, (a.y-mean)*inv*g0.y + b0.y);
    o.y = packh2((a.z-mean)*inv*g0.z + b0.z, (a.w-mean)*inv*g0.w + b0.w);
    o.z = packh2((c.x-mean)*inv*g1.x + b1.x, (c.y-mean)*inv*g1.y + b1.y);
    o.w = packh2((c.z-mean)*inv*g1.z + b1.z, (c.w-mean)*inv*g1.w + b1.w);
    ((uint4*)(g_win + r * 256))[lane] = o;
}

// ---------------- tensor-core windowed attention ----------------
#define AT_STR 72
__global__ __launch_bounds__(128) void k_attn_tc(const float* __restrict__ rpb, int shift) {
    int w  = blockIdx.x >> 2;
    int hp = blockIdx.x & 3;
    __shared__ __half sq[64 * AT_STR];
    __shared__ __half sk[64 * AT_STR];
    __shared__ __half sv[64 * AT_STR];
    __shared__ float  srpb[686];
    __shared__ int    slab[64];

    const int tid = threadIdx.x;
    const int lane = tid & 31, wid = tid >> 5;

    #pragma unroll
    for (int j = 0; j < 4; j++) {
        int c = tid + j * 128;
        int tok = c >> 3, cg = c & 7;
        const __half* base = g_qkv + (size_t)(w * 64 + tok) * 768 + hp * 64 + cg * 8;
        cp16(&sq[tok * AT_STR + cg * 8], base);
        cp16(&sk[tok * AT_STR + cg * 8], base + 256);
    }
    asm volatile("cp.async.commit_group;\n" ::: "memory");
    #pragma unroll
    for (int j = 0; j < 16; j++) {
        int e = tid + j * 128;
        int tok = e >> 5, dp = e & 31;
        __half2 v = *(const __half2*)(g_qkv + (size_t)(w * 64 + tok) * 768 + 512 + hp * 64 + dp * 2);
        sv[(dp * 2 + 0) * AT_STR + tok] = __low2half(v);
        sv[(dp * 2 + 1) * AT_STR + tok] = __high2half(v);
    }
    for (int i = tid; i < 686; i += 128)
        srpb[i] = rpb[(i % 343) * 8 + hp * 2 + (i / 343)];
    if (tid < 64) {
        int n = tid;
        int gh = ((w >> 6) << 2)       + (n >> 4);
        int gw = (((w >> 3) & 7) << 2) + ((n >> 2) & 3);
        int gt = ((w & 7) << 2)        + (n & 3);
        int rh = (gh < 28) ? 0 : ((gh < 30) ? 1 : 2);
        int rw = (gw < 28) ? 0 : ((gw < 30) ? 1 : 2);
        int rt = (gt < 28) ? 0 : ((gt < 30) ? 1 : 2);
        slab[n] = rh * 9 + rw * 3 + rt;
    }
    asm volatile("cp.async.wait_group 0;\n" ::: "memory");
    __syncthreads();

    const int hsel  = wid >> 1;
    const int mbase = (wid & 1) * 32;
    const int h     = hp * 2 + hsel;
    const int hoff  = hsel * 32;

    float acc[2][8][4];
    #pragma unroll
    for (int mt = 0; mt < 2; mt++)
        #pragma unroll
        for (int nt = 0; nt < 8; nt++)
            #pragma unroll
            for (int r = 0; r < 4; r++) acc[mt][nt][r] = 0.f;

    #pragma unroll
    for (int kc = 0; kc < 2; kc++) {
        unsigned a[2][4];
        #pragma unroll
        for (int mt = 0; mt < 2; mt++) {
            int t = lane >> 3;
            int row = mbase + mt * 16 + (t & 1) * 8 + (lane & 7);
            int col = hoff + kc * 16 + (t >> 1) * 8;
            ldsm4(a[mt], smem_u32(&sq[row * AT_STR + col]));
        }
        #pragma unroll
        for (int nt = 0; nt < 8; nt++) {
            unsigned b[2];
            int row = nt * 8 + (lane & 7);
            int col = hoff + kc * 16 + ((lane >> 3) & 1) * 8;
            ldsm2(b, smem_u32(&sk[row * AT_STR + col]));
            #pragma unroll
            for (int mt = 0; mt < 2; mt++) mma_f16(acc[mt][nt], a[mt], b);
        }
    }

    int rh4[4], rw4[4], rt4[4], rlab[4];
    #pragma unroll
    for (int i = 0; i < 4; i++) {
        int tok = mbase + (i >> 1) * 16 + (i & 1) * 8 + (lane >> 2);
        rh4[i] = tok >> 4; rw4[i] = (tok >> 2) & 3; rt4[i] = tok & 3;
        rlab[i] = slab[tok];
    }
    #pragma unroll
    for (int mt = 0; mt < 2; mt++)
        #pragma unroll
        for (int nt = 0; nt < 8; nt++)
            #pragma unroll
            for (int r = 0; r < 4; r++) {
                int i  = mt * 2 + (r >> 1);
                int cn = nt * 8 + ((lane & 3) << 1) + (r & 1);
                int idx = ((rh4[i] - (cn >> 4) + 3) * 7 + (rw4[i] - ((cn >> 2) & 3) + 3)) * 7
                        + (rt4[i] - (cn & 3) + 3);
                float s = acc[mt][nt][r] * 0.17677669529663687f + srpb[hsel * 343 + idx];
                if (shift && rlab[i] != slab[cn]) s -= 100.f;
                acc[mt][nt][r] = s;
            }

    float mx[4] = {-1e30f, -1e30f, -1e30f, -1e30f};
    #pragma unroll
    for (int mt = 0; mt < 2; mt++)
        #pragma unroll
        for (int nt = 0; nt < 8; nt++)
            #pragma unroll
            for (int r = 0; r < 4; r++)
                mx[mt * 2 + (r >> 1)] = fmaxf(mx[mt * 2 + (r >> 1)], acc[mt][nt][r]);
    #pragma unroll
    for (int i = 0; i < 4; i++) {
        mx[i] = fmaxf(mx[i], __shfl_xor_sync(0xffffffffu, mx[i], 1));
        mx[i] = fmaxf(mx[i], __shfl_xor_sync(0xffffffffu, mx[i], 2));
    }
    float sm[4] = {0.f, 0.f, 0.f, 0.f};
    #pragma unroll
    for (int mt = 0; mt < 2; mt++)
        #pragma unroll
        for (int nt = 0; nt < 8; nt++)
            #pragma unroll
            for (int r = 0; r < 4; r++) {
                float p = __expf(acc[mt][nt][r] - mx[mt * 2 + (r >> 1)]);
                acc[mt][nt][r] = p;
                sm[mt * 2 + (r >> 1)] += p;
            }
    #pragma unroll
    for (int i = 0; i < 4; i++) {
        sm[i] += __shfl_xor_sync(0xffffffffu, sm[i], 1);
        sm[i] += __shfl_xor_sync(0xffffffffu, sm[i], 2);
    }

    float acc2[2][4][4];
    #pragma unroll
    for (int mt = 0; mt < 2; mt++)
        #pragma unroll
        for (int nt = 0; nt < 4; nt++)
            #pragma unroll
            for (int r = 0; r < 4; r++) acc2[mt][nt][r] = 0.f;

    #pragma unroll
    for (int kc = 0; kc < 4; kc++) {
        unsigned ah[2][4];
        #pragma unroll
        for (int mt = 0; mt < 2; mt++) {
            ah[mt][0] = packh2(acc[mt][2*kc  ][0], acc[mt][2*kc  ][1]);
            ah[mt][1] = packh2(acc[mt][2*kc  ][2], acc[mt][2*kc  ][3]);
            ah[mt][2] = packh2(acc[mt][2*kc+1][0], acc[mt][2*kc+1][1]);
            ah[mt][3] = packh2(acc[mt][2*kc+1][2], acc[mt][2*kc+1][3]);
        }
        #pragma unroll
        for (int nt = 0; nt < 4; nt++) {
            unsigned b[2];
            int row = hoff + nt * 8 + (lane & 7);
            int col = kc * 16 + ((lane >> 3) & 1) * 8;
            ldsm2(b, smem_u32(&sv[row * AT_STR + col]));
            #pragma unroll
            for (int mt = 0; mt < 2; mt++) mma_f16(acc2[mt][nt], ah[mt], b);
        }
    }

    #pragma unroll
    for (int mt = 0; mt < 2; mt++)
        #pragma unroll
        for (int hf = 0; hf < 2; hf++) {
            float inv = 1.f / sm[mt * 2 + hf];
            int tok = mbase + mt * 16 + hf * 8 + (lane >> 2);
            __half* op = g_att + (size_t)(w * 64 + tok) * 256 + h * 32 + ((lane & 3) << 1);
            #pragma unroll
            for (int nt = 0; nt < 4; nt++) {
                unsigned hv = packh2(acc2[mt][nt][hf * 2] * inv, acc2[mt][nt][hf * 2 + 1] * inv);
                *(unsigned*)(op + nt * 8) = hv;
            }
        }
}

// ---------------- fp16 tensor-core NT GEMM (128x256 tile, 8 warps of 64x64) ----------------
// K-step 64 halves (128B rows, XOR-8 swizzle), 3-stage cp.async pipeline,
// single __syncthreads per k-tile. EPI 0: +bias fp16  1: +bias GELU fp16  2: scatter-add  3: add
#define GSTG 24576   // halves per stage: A 128x64 (8192) + B 256x64 (16384)
template<int EPI, typename OutT>
__global__ __launch_bounds__(256) void k_gemm(const __half* __restrict__ A,
                                              const __half* __restrict__ B,
                                              const float* __restrict__ bias,
                                              OutT* __restrict__ Cout,
                                              int N, int K, int shift) {
    extern __shared__ __half smem[];          // 3 stages * 48 KB
    const int t = threadIdx.x;
    const int lane = t & 31, wid = t >> 5;
    const int mb = (wid & 1) * 64, nb = (wid >> 1) * 64;
    const int rowBase = blockIdx.y << 7;
    const int colBase = blockIdx.x << 8;

    float acc[4][8][4];
    #pragma unroll
    for (int mt = 0; mt < 4; mt++)
        #pragma unroll
        for (int nt = 0; nt < 8; nt++)
            #pragma unroll
            for (int r = 0; r < 4; r++) acc[mt][nt][r] = 0.f;

    auto load_tile = [&](int buf, int k0) {
        __half* sa = smem + buf * GSTG;
        __half* sb = sa + 8192;
        #pragma unroll
        for (int j = 0; j < 4; j++) {
            int idx = t + j * 256;            // A: 1024 chunks of 16B
            int row = idx >> 3, ch = idx & 7;
            cp16(&sa[row * 64 + ((ch ^ (row & 7)) << 3)],
                 A + (size_t)(rowBase + row) * K + k0 + ch * 8);
        }
        #pragma unroll
        for (int j = 0; j < 8; j++) {
            int idx = t + j * 256;            // B: 2048 chunks
            int row = idx >> 3, ch = idx & 7;
            cp16(&sb[row * 64 + ((ch ^ (row & 7)) << 3)],
                 B + (size_t)(colBase + row) * K + k0 + ch * 8);
        }
        asm volatile("cp.async.commit_group;\n" ::: "memory");
    };

    const int ntiles = K >> 6;
    load_tile(0, 0);
    load_tile(1, 64);
    for (int i = 0; i < ntiles; i++) {
        if (i + 1 < ntiles) {
            asm volatile("cp.async.wait_group 1;\n" ::: "memory");
        } else {
            asm volatile("cp.async.wait_group 0;\n" ::: "memory");
        }
        __syncthreads();
        if (i + 2 < ntiles) load_tile((i + 2) % 3, (i + 2) << 6);
        const __half* sa = smem + (i % 3) * GSTG;
        const __half* sb = sa + 8192;
        #pragma unroll
        for (int ks = 0; ks < 4; ks++) {
            unsigned af[4][4];
            #pragma unroll
            for (int mt = 0; mt < 4; mt++) {
                int tq = lane >> 3;
                int row = mb + mt * 16 + (tq & 1) * 8 + (lane & 7);
                int ch = ks * 2 + (tq >> 1);
                ldsm4(af[mt], smem_u32(&sa[row * 64 + ((ch ^ (row & 7)) << 3)]));
            }
            unsigned bf[8][2];
            #pragma unroll
            for (int np = 0; np < 4; np++) {
                int row = nb + np * 16 + ((lane >> 4) & 1) * 8 + (lane & 7);
                int ch = ks * 2 + ((lane >> 3) & 1);
                unsigned b4[4];
                ldsm4(b4, smem_u32(&sb[row * 64 + ((ch ^ (row & 7)) << 3)]));
                bf[np*2][0]   = b4[0]; bf[np*2][1]   = b4[1];
                bf[np*2+1][0] = b4[2]; bf[np*2+1][1] = b4[3];
            }
            #pragma unroll
            for (int mt = 0; mt < 4; mt++)
                #pragma unroll
                for (int nt = 0; nt < 8; nt++)
                    mma_f16(acc[mt][nt], af[mt], bf[nt]);
        }
    }

    float2 bv[8];
    #pragma unroll
    for (int nt = 0; nt < 8; nt++)
        bv[nt] = *(const float2*)(bias + colBase + nb + nt * 8 + (lane & 3) * 2);

    #pragma unroll
    for (int mt = 0; mt < 4; mt++) {
        #pragma unroll
        for (int i = 0; i < 2; i++) {
            int row = rowBase + mb + mt * 16 + (lane >> 2) + i * 8;
            int dst = (EPI == 2) ? win_to_tok(row, shift) : row;
            #pragma unroll
            for (int nt = 0; nt < 8; nt++) {
                int col = colBase + nb + nt * 8 + (lane & 3) * 2;
                float v0 = acc[mt][nt][i * 2 + 0] + bv[nt].x;
                float v1 = acc[mt][nt][i * 2 + 1] + bv[nt].y;
                if (EPI == 0) {
                    *(unsigned*)((__half*)Cout + (size_t)row * N + col) = packh2(v0, v1);
                } else if (EPI == 1) {
                    v0 = 0.5f * v0 * (1.0f + erff(v0 * 0.70710678118654752f));
                    v1 = 0.5f * v1 * (1.0f + erff(v1 * 0.70710678118654752f));
                    *(unsigned*)((__half*)Cout + (size_t)row * N + col) = packh2(v0, v1);
                } else {
                    float2* rp = (float2*)(g_x + dst * 256 + col);
                    float2 r0 = *rp;
                    r0.x += v0; r0.y += v1;
                    *rp = r0;
                }
            }
        }
    }
}

// ---------------- final LN + [L,C] -> [C,L] transpose ----------------
__global__ __launch_bounds__(256) void k_final(const float* __restrict__ gam,
                                               const float* __restrict__ bet,
                                               float* __restrict__ out) {
    __shared__ float sm[256][33];
    int warp = threadIdx.x >> 5, lane = threadIdx.x & 31;
    int l0 = blockIdx.x << 5;
    float4 g0 = ((const float4*)gam)[lane*2], g1 = ((const float4*)gam)[lane*2+1];
    float4 b0 = ((const float4*)bet)[lane*2], b1 = ((const float4*)bet)[lane*2+1];
    #pragma unroll
    for (int i = 0; i < 4; i++) {
        int tok = (warp << 2) + i;
        const float4* xp = (const float4*)(g_x + (l0 + tok) * 256);
        float4 a = xp[lane*2], c = xp[lane*2+1];
        float s  = a.x + a.y + a.z + a.w + c.x + c.y + c.z + c.w;
        float sq = a.x*a.x + a.y*a.y + a.z*a.z + a.w*a.w
                 + c.x*c.x + c.y*c.y + c.z*c.z + c.w*c.w;
        #pragma unroll
        for (int o = 16; o; o >>= 1) {
            s  += __shfl_xor_sync(0xffffffffu, s, o);
            sq += __shfl_xor_sync(0xffffffffu, sq, o);
        }
        float mean = s * (1.0f / 256.0f);
        float inv = rsqrtf(sq * (1.0f / 256.0f) - mean * mean + 1e-5f);
        int cb = lane * 8;
        sm[cb+0][tok] = (a.x-mean)*inv*g0.x + b0.x;
        sm[cb+1][tok] = (a.y-mean)*inv*g0.y + b0.y;
        sm[cb+2][tok] = (a.z-mean)*inv*g0.z + b0.z;
        sm[cb+3][tok] = (a.w-mean)*inv*g0.w + b0.w;
        sm[cb+4][tok] = (c.x-mean)*inv*g1.x + b1.x;
        sm[cb+5][tok] = (c.y-mean)*inv*g1.y + b1.y;
        sm[cb+6][tok] = (c.z-mean)*inv*g1.z + b1.z;
        sm[cb+7][tok] = (c.w-mean)*inv*g1.w + b1.w;
    }
    __syncthreads();
    int lt = threadIdx.x & 31;
    int cw = threadIdx.x >> 5;
    #pragma unroll
    for (int cc = 0; cc < 32; cc++) {
        int c = (cc << 3) + cw;
        out[c * L_TOK + l0 + lt] = sm[c][lt];
    }
}

// ---------------- launch ----------------
#define GEMM_SMEM (3 * GSTG * 2)
extern "C" void kernel_launch(void* const* d_in, const int* in_sizes, int n_in,
                              void* d_out, int out_size) {
    const float* x      = (const float*)d_in[0];
    const float* norm_g = (const float*)d_in[4];
    const float* norm_b = (const float*)d_in[5];
    float* out = (float*)d_out;

    __half *p_win, *p_qkv, *p_att, *p_mlp, *p_w;
    cudaGetSymbolAddress((void**)&p_win, g_win);
    cudaGetSymbolAddress((void**)&p_qkv, g_qkv);
    cudaGetSymbolAddress((void**)&p_att, g_att);
    cudaGetSymbolAddress((void**)&p_mlp, g_mlp);
    cudaGetSymbolAddress((void**)&p_w,   g_wbuf);

    cudaFuncSetAttribute(k_gemm<0, __half>, cudaFuncAttributeMaxDynamicSharedMemorySize, GEMM_SMEM);
    cudaFuncSetAttribute(k_gemm<1, __half>, cudaFuncAttributeMaxDynamicSharedMemorySize, GEMM_SMEM);
    cudaFuncSetAttribute(k_gemm<2, float >, cudaFuncAttributeMaxDynamicSharedMemorySize, GEMM_SMEM);
    cudaFuncSetAttribute(k_gemm<3, float >, cudaFuncAttributeMaxDynamicSharedMemorySize, GEMM_SMEM);

    k_copy<<<8192, 256>>>(x);
    k_roundall<<<1536, 256>>>((const float*)d_in[8],  (const float*)d_in[11],
                              (const float*)d_in[15], (const float*)d_in[17],
                              (const float*)d_in[21], (const float*)d_in[24],
                              (const float*)d_in[28], (const float*)d_in[30]);

    for (int blk = 0; blk < 2; blk++) {
        int o = 6 + blk * 13;
        int shift = blk ? 2 : 0;
        const float* n1g   = (const float*)d_in[o+0];
        const float* n1b   = (const float*)d_in[o+1];
        const float* qkvb  = (const float*)d_in[o+3];
        const float* rpb   = (const float*)d_in[o+4];
        const float* projb = (const float*)d_in[o+6];
        const float* n2g   = (const float*)d_in[o+7];
        const float* n2b   = (const float*)d_in[o+8];
        const float* fc1b  = (const float*)d_in[o+10];
        const float* fc2b  = (const float*)d_in[o+12];
        __half* wbase = p_w + blk * 786432;

        k_ln<1><<<4096, 256>>>(n1g, n1b, shift);
        k_gemm<0, __half><<<dim3(3, 256), 256, GEMM_SMEM>>>(p_win, wbase,          qkvb,  p_qkv, 768, 256, 0);
        k_attn_tc<<<2048, 128>>>(rpb, shift);
        k_gemm<2, float ><<<dim3(1, 256), 256, GEMM_SMEM>>>(p_att, wbase + 196608, projb, (float*)nullptr, 256, 256, shift);
        k_ln<0><<<4096, 256>>>(n2g, n2b, 0);
        k_gemm<1, __half><<<dim3(4, 256), 256, GEMM_SMEM>>>(p_win, wbase + 262144, fc1b,  p_mlp, 1024, 256, 0);
        k_gemm<3, float ><<<dim3(1, 256), 256, GEMM_SMEM>>>(p_mlp, wbase + 524288, fc2b,  (float*)nullptr, 256, 1024, 0);
    }

    k_final<<<1024, 256>>>(norm_g, norm_b, out);
}

// round 12
// speedup vs baseline: 1.0925x; 1.0925x over previous
#include <cuda_runtime.h>
#include <cuda_fp16.h>
#include <math.h>

#define L_TOK 32768

// ---------------- scratch (device globals; no runtime allocation) ----------------
__device__ float  g_x  [L_TOK * 256];   // residual stream (fp32)
__device__ __half g_win[L_TOK * 256];   // LN output / partitioned windows (fp16)
__device__ __half g_qkv[L_TOK * 768];   // qkv (fp16)
__device__ __half g_att[L_TOK * 256];   // attention out (fp16, window layout)
__device__ __half g_mlp[L_TOK * 1024];  // MLP hidden (fp16)
__device__ __half g_wbuf[2 * 786432];   // fp16 weights

__device__ __forceinline__ int win_to_tok(int r, int shift) {
    int w = r >> 6, n = r & 63;
    int h  = ((w >> 6) << 2)        + (n >> 4);
    int wy = (((w >> 3) & 7) << 2)  + ((n >> 2) & 3);
    int t  = ((w & 7) << 2)         + (n & 3);
    h  = (h  + shift) & 31;
    wy = (wy + shift) & 31;
    t  = (t  + shift) & 31;
    return (h << 10) + (wy << 5) + t;
}

__device__ __forceinline__ void cp16(void* s, const void* g) {
    unsigned sa = (unsigned)__cvta_generic_to_shared(s);
    asm volatile("cp.async.cg.shared.global [%0], [%1], 16;\n" :: "r"(sa), "l"(g));
}
__device__ __forceinline__ unsigned smem_u32(const void* p) {
    unsigned a;
    asm("{ .reg .u64 t; cvta.to.shared.u64 t, %1; cvt.u32.u64 %0, t; }" : "=r"(a) : "l"(p));
    return a;
}
__device__ __forceinline__ void mma_f16(float* d, const unsigned* a, const unsigned* b) {
    asm volatile(
        "mma.sync.aligned.m16n8k16.row.col.f32.f16.f16.f32 "
        "{%0,%1,%2,%3}, {%4,%5,%6,%7}, {%8,%9}, {%0,%1,%2,%3};\n"
        : "+f"(d[0]), "+f"(d[1]), "+f"(d[2]), "+f"(d[3])
        : "r"(a[0]), "r"(a[1]), "r"(a[2]), "r"(a[3]), "r"(b[0]), "r"(b[1]));
}
__device__ __forceinline__ void ldsm4(unsigned* r, unsigned addr) {
    asm volatile("ldmatrix.sync.aligned.m8n8.x4.shared.b16 {%0,%1,%2,%3}, [%4];"
        : "=r"(r[0]), "=r"(r[1]), "=r"(r[2]), "=r"(r[3]) : "r"(addr));
}
__device__ __forceinline__ void ldsm2(unsigned* r, unsigned addr) {
    asm volatile("ldmatrix.sync.aligned.m8n8.x2.shared.b16 {%0,%1}, [%2];"
        : "=r"(r[0]), "=r"(r[1]) : "r"(addr));
}
__device__ __forceinline__ unsigned packh2(float a, float b) {
    __half2 h = __floats2half2_rn(a, b);
    return *(unsigned*)&h;
}

// ---------------- residual init ----------------
__global__ void k_copy(const float* __restrict__ src) {
    int i = blockIdx.x * 256 + threadIdx.x;
    ((float4*)g_x)[i] = ((const float4*)src)[i];
}

// ---------------- fp16 weight conversion (all 8 weight tensors, one launch) ----------------
__global__ void k_roundall(const float* s0, const float* s1, const float* s2, const float* s3,
                           const float* s4, const float* s5, const float* s6, const float* s7) {
    int i = blockIdx.x * 256 + threadIdx.x;            // 0 .. 393215 (float4 units)
    int set = i >= 196608;
    int j = set ? i - 196608 : i;
    const float* src;
    int dstoff;
    if      (j <  49152) { src = set ? s4 : s0; dstoff = j; }
    else if (j <  65536) { src = set ? s5 : s1; dstoff = (196608 >> 2) + (j - 49152); }
    else if (j < 131072) { src = set ? s6 : s2; dstoff = (262144 >> 2) + (j - 65536); }
    else                 { src = set ? s7 : s3; dstoff = (524288 >> 2) + (j - 131072); }
    int local = (j < 49152) ? j : (j < 65536) ? j - 49152 : (j < 131072) ? j - 65536 : j - 131072;
    float4 v = ((const float4*)src)[local];
    uint2 o;
    o.x = packh2(v.x, v.y);
    o.y = packh2(v.z, v.w);
    ((uint2*)(g_wbuf + set * 786432))[dstoff] = o;
}

// ---------------- LayerNorm (REMAP=1: fused shift+partition gather); fp16 out ----------------
template<int REMAP>
__global__ __launch_bounds__(256) void k_ln(const float* __restrict__ gam,
                                            const float* __restrict__ bet, int shift) {
    int warp = threadIdx.x >> 5, lane = threadIdx.x & 31;
    int r = (blockIdx.x << 3) + warp;
    int src = REMAP ? win_to_tok(r, shift) : r;
    const float4* xp = (const float4*)(g_x + src * 256);
    float4 a = xp[lane * 2], c = xp[lane * 2 + 1];
    float s  = a.x + a.y + a.z + a.w + c.x + c.y + c.z + c.w;
    float sq = a.x*a.x + a.y*a.y + a.z*a.z + a.w*a.w
             + c.x*c.x + c.y*c.y + c.z*c.z + c.w*c.w;
    #pragma unroll
    for (int o = 16; o; o >>= 1) {
        s  += __shfl_xor_sync(0xffffffffu, s, o);
        sq += __shfl_xor_sync(0xffffffffu, sq, o);
    }
    float mean = s * (1.0f / 256.0f);
    float inv = rsqrtf(sq * (1.0f / 256.0f) - mean * mean + 1e-5f);
    float4 g0 = ((const float4*)gam)[lane*2], g1 = ((const float4*)gam)[lane*2+1];
    float4 b0 = ((const float4*)bet)[lane*2], b1 = ((const float4*)bet)[lane*2+1];
    uint4 o;
    o.x = packh2((a.x-mean)*inv*g0.x + b0.x, (a.y-mean)*inv*g0.y + b0.y);
    o.y = packh2((a.z-mean)*inv*g0.z + b0.z, (a.w-mean)*inv*g0.w + b0.w);
    o.z = packh2((c.x-mean)*inv*g1.x + b1.x, (c.y-mean)*inv*g1.y + b1.y);
    o.w = packh2((c.z-mean)*inv*g1.z + b1.z, (c.w-mean)*inv*g1.w + b1.w);
    ((uint4*)(g_win + r * 256))[lane] = o;
}

// ---------------- tensor-core windowed attention ----------------
#define AT_STR 72
__global__ __launch_bounds__(128) void k_attn_tc(const float* __restrict__ rpb, int shift) {
    int w  = blockIdx.x >> 2;
    int hp = blockIdx.x & 3;
    __shared__ __half sq[64 * AT_STR];
    __shared__ __half sk[64 * AT_STR];
    __shared__ __half sv[64 * AT_STR];
    __shared__ float  srpb[686];
    __shared__ int    slab[64];

    const int tid = threadIdx.x;
    const int lane = tid & 31, wid = tid >> 5;

    #pragma unroll
    for (int j = 0; j < 4; j++) {
        int c = tid + j * 128;
        int tok = c >> 3, cg = c & 7;
        const __half* base = g_qkv + (size_t)(w * 64 + tok) * 768 + hp * 64 + cg * 8;
        cp16(&sq[tok * AT_STR + cg * 8], base);
        cp16(&sk[tok * AT_STR + cg * 8], base + 256);
    }
    asm volatile("cp.async.commit_group;\n" ::: "memory");
    #pragma unroll
    for (int j = 0; j < 16; j++) {
        int e = tid + j * 128;
        int tok = e >> 5, dp = e & 31;
        __half2 v = *(const __half2*)(g_qkv + (size_t)(w * 64 + tok) * 768 + 512 + hp * 64 + dp * 2);
        sv[(dp * 2 + 0) * AT_STR + tok] = __low2half(v);
        sv[(dp * 2 + 1) * AT_STR + tok] = __high2half(v);
    }
    for (int i = tid; i < 686; i += 128)
        srpb[i] = rpb[(i % 343) * 8 + hp * 2 + (i / 343)];
    if (tid < 64) {
        int n = tid;
        int gh = ((w >> 6) << 2)       + (n >> 4);
        int gw = (((w >> 3) & 7) << 2) + ((n >> 2) & 3);
        int gt = ((w & 7) << 2)        + (n & 3);
        int rh = (gh < 28) ? 0 : ((gh < 30) ? 1 : 2);
        int rw = (gw < 28) ? 0 : ((gw < 30) ? 1 : 2);
        int rt = (gt < 28) ? 0 : ((gt < 30) ? 1 : 2);
        slab[n] = rh * 9 + rw * 3 + rt;
    }
    asm volatile("cp.async.wait_group 0;\n" ::: "memory");
    __syncthreads();

    const int hsel  = wid >> 1;
    const int mbase = (wid & 1) * 32;
    const int h     = hp * 2 + hsel;
    const int hoff  = hsel * 32;

    float acc[2][8][4];
    #pragma unroll
    for (int mt = 0; mt < 2; mt++)
        #pragma unroll
        for (int nt = 0; nt < 8; nt++)
            #pragma unroll
            for (int r = 0; r < 4; r++) acc[mt][nt][r] = 0.f;

    #pragma unroll
    for (int kc = 0; kc < 2; kc++) {
        unsigned a[2][4];
        #pragma unroll
        for (int mt = 0; mt < 2; mt++) {
            int t = lane >> 3;
            int row = mbase + mt * 16 + (t & 1) * 8 + (lane & 7);
            int col = hoff + kc * 16 + (t >> 1) * 8;
            ldsm4(a[mt], smem_u32(&sq[row * AT_STR + col]));
        }
        #pragma unroll
        for (int nt = 0; nt < 8; nt++) {
            unsigned b[2];
            int row = nt * 8 + (lane & 7);
            int col = hoff + kc * 16 + ((lane >> 3) & 1) * 8;
            ldsm2(b, smem_u32(&sk[row * AT_STR + col]));
            #pragma unroll
            for (int mt = 0; mt < 2; mt++) mma_f16(acc[mt][nt], a[mt], b);
        }
    }

    int rh4[4], rw4[4], rt4[4], rlab[4];
    #pragma unroll
    for (int i = 0; i < 4; i++) {
        int tok = mbase + (i >> 1) * 16 + (i & 1) * 8 + (lane >> 2);
        rh4[i] = tok >> 4; rw4[i] = (tok >> 2) & 3; rt4[i] = tok & 3;
        rlab[i] = slab[tok];
    }
    #pragma unroll
    for (int mt = 0; mt < 2; mt++)
        #pragma unroll
        for (int nt = 0; nt < 8; nt++)
            #pragma unroll
            for (int r = 0; r < 4; r++) {
                int i  = mt * 2 + (r >> 1);
                int cn = nt * 8 + ((lane & 3) << 1) + (r & 1);
                int idx = ((rh4[i] - (cn >> 4) + 3) * 7 + (rw4[i] - ((cn >> 2) & 3) + 3)) * 7
                        + (rt4[i] - (cn & 3) + 3);
                float s = acc[mt][nt][r] * 0.17677669529663687f + srpb[hsel * 343 + idx];
                if (shift && rlab[i] != slab[cn]) s -= 100.f;
                acc[mt][nt][r] = s;
            }

    float mx[4] = {-1e30f, -1e30f, -1e30f, -1e30f};
    #pragma unroll
    for (int mt = 0; mt < 2; mt++)
        #pragma unroll
        for (int nt = 0; nt < 8; nt++)
            #pragma unroll
            for (int r = 0; r < 4; r++)
                mx[mt * 2 + (r >> 1)] = fmaxf(mx[mt * 2 + (r >> 1)], acc[mt][nt][r]);
    #pragma unroll
    for (int i = 0; i < 4; i++) {
        mx[i] = fmaxf(mx[i], __shfl_xor_sync(0xffffffffu, mx[i], 1));
        mx[i] = fmaxf(mx[i], __shfl_xor_sync(0xffffffffu, mx[i], 2));
    }
    float sm[4] = {0.f, 0.f, 0.f, 0.f};
    #pragma unroll
    for (int mt = 0; mt < 2; mt++)
        #pragma unroll
        for (int nt = 0; nt < 8; nt++)
            #pragma unroll
            for (int r = 0; r < 4; r++) {
                float p = __expf(acc[mt][nt][r] - mx[mt * 2 + (r >> 1)]);
                acc[mt][nt][r] = p;
                sm[mt * 2 + (r >> 1)] += p;
            }
    #pragma unroll
    for (int i = 0; i < 4; i++) {
        sm[i] += __shfl_xor_sync(0xffffffffu, sm[i], 1);
        sm[i] += __shfl_xor_sync(0xffffffffu, sm[i], 2);
    }

    float acc2[2][4][4];
    #pragma unroll
    for (int mt = 0; mt < 2; mt++)
        #pragma unroll
        for (int nt = 0; nt < 4; nt++)
            #pragma unroll
            for (int r = 0; r < 4; r++) acc2[mt][nt][r] = 0.f;

    #pragma unroll
    for (int kc = 0; kc < 4; kc++) {
        unsigned ah[2][4];
        #pragma unroll
        for (int mt = 0; mt < 2; mt++) {
            ah[mt][0] = packh2(acc[mt][2*kc  ][0], acc[mt][2*kc  ][1]);
            ah[mt][1] = packh2(acc[mt][2*kc  ][2], acc[mt][2*kc  ][3]);
            ah[mt][2] = packh2(acc[mt][2*kc+1][0], acc[mt][2*kc+1][1]);
            ah[mt][3] = packh2(acc[mt][2*kc+1][2], acc[mt][2*kc+1][3]);
        }
        #pragma unroll
        for (int nt = 0; nt < 4; nt++) {
            unsigned b[2];
            int row = hoff + nt * 8 + (lane & 7);
            int col = kc * 16 + ((lane >> 3) & 1) * 8;
            ldsm2(b, smem_u32(&sv[row * AT_STR + col]));
            #pragma unroll
            for (int mt = 0; mt < 2; mt++) mma_f16(acc2[mt][nt], ah[mt], b);
        }
    }

    #pragma unroll
    for (int mt = 0; mt < 2; mt++)
        #pragma unroll
        for (int hf = 0; hf < 2; hf++) {
            float inv = 1.f / sm[mt * 2 + hf];
            int tok = mbase + mt * 16 + hf * 8 + (lane >> 2);
            __half* op = g_att + (size_t)(w * 64 + tok) * 256 + h * 32 + ((lane & 3) << 1);
            #pragma unroll
            for (int nt = 0; nt < 4; nt++) {
                unsigned hv = packh2(acc2[mt][nt][hf * 2] * inv, acc2[mt][nt][hf * 2 + 1] * inv);
                *(unsigned*)(op + nt * 8) = hv;
            }
        }
}

// ---------------- fp16 tensor-core NT GEMM (128x128, 8 warps of 32x64) ----------------
// K-step 64 halves (128B rows, XOR-8 swizzle), 3-stage cp.async pipeline with a single
// __syncthreads per k-tile, B-fragments double-buffered across k-steps.
// EPI 0: +bias fp16  1: +bias GELU fp16  2: scatter-add residual  3: add residual
#define GSTG 16384   // halves per stage: A 128x64 (8192) + B 128x64 (8192)
template<int EPI, typename OutT>
__global__ __launch_bounds__(256, 2) void k_gemm(const __half* __restrict__ A,
                                                 const __half* __restrict__ B,
                                                 const float* __restrict__ bias,
                                                 OutT* __restrict__ Cout,
                                                 int N, int K, int shift) {
    extern __shared__ __half smem[];          // 3 stages * 32 KB
    const int t = threadIdx.x;
    const int lane = t & 31, wid = t >> 5;
    const int warp_m = wid & 3, warp_n = wid >> 2;
    const int rowBase = blockIdx.y << 7;
    const int colBase = blockIdx.x << 7;
    const int mb = warp_m * 32, nb = warp_n * 64;

    float acc[2][8][4];
    #pragma unroll
    for (int mt = 0; mt < 2; mt++)
        #pragma unroll
        for (int nt = 0; nt < 8; nt++)
            #pragma unroll
            for (int r = 0; r < 4; r++) acc[mt][nt][r] = 0.f;

    auto load_tile = [&](int buf, int k0) {
        __half* sa = smem + buf * GSTG;
        __half* sb = sa + 8192;
        #pragma unroll
        for (int j = 0; j < 4; j++) {
            int idx = t + j * 256;            // A: 1024 chunks of 16B
            int row = idx >> 3, ch = idx & 7;
            cp16(&sa[row * 64 + ((ch ^ (row & 7)) << 3)],
                 A + (size_t)(rowBase + row) * K + k0 + ch * 8);
        }
        #pragma unroll
        for (int j = 0; j < 4; j++) {
            int idx = t + j * 256;            // B: 1024 chunks
            int row = idx >> 3, ch = idx & 7;
            cp16(&sb[row * 64 + ((ch ^ (row & 7)) << 3)],
                 B + (size_t)(colBase + row) * K + k0 + ch * 8);
        }
        asm volatile("cp.async.commit_group;\n" ::: "memory");
    };

    auto loadB = [&](const __half* sb, int ks, unsigned (*bf)[2]) {
        #pragma unroll
        for (int np = 0; np < 4; np++) {
            int row = nb + np * 16 + ((lane >> 4) & 1) * 8 + (lane & 7);
            int ch = ks * 2 + ((lane >> 3) & 1);
            unsigned b4[4];
            ldsm4(b4, smem_u32(&sb[row * 64 + ((ch ^ (row & 7)) << 3)]));
            bf[np*2][0]   = b4[0]; bf[np*2][1]   = b4[1];
            bf[np*2+1][0] = b4[2]; bf[np*2+1][1] = b4[3];
        }
    };

    const int ntiles = K >> 6;
    load_tile(0, 0);
    load_tile(1, 64);
    for (int i = 0; i < ntiles; i++) {
        if (i + 1 < ntiles) {
            asm volatile("cp.async.wait_group 1;\n" ::: "memory");
        } else {
            asm volatile("cp.async.wait_group 0;\n" ::: "memory");
        }
        __syncthreads();
        if (i + 2 < ntiles) load_tile((i + 2) % 3, (i + 2) << 6);
        const __half* sa = smem + (i % 3) * GSTG;
        const __half* sb = sa + 8192;

        unsigned bf[2][8][2];
        loadB(sb, 0, bf[0]);
        #pragma unroll
        for (int ks = 0; ks < 4; ks++) {
            if (ks < 3) loadB(sb, ks + 1, bf[(ks + 1) & 1]);   // overlap next B-frags with MMAs
            unsigned af[2][4];
            #pragma unroll
            for (int mt = 0; mt < 2; mt++) {
                int tq = lane >> 3;
                int row = mb + mt * 16 + (tq & 1) * 8 + (lane & 7);
                int ch = ks * 2 + (tq >> 1);
                ldsm4(af[mt], smem_u32(&sa[row * 64 + ((ch ^ (row & 7)) << 3)]));
            }
            #pragma unroll
            for (int mt = 0; mt < 2; mt++)
                #pragma unroll
                for (int nt = 0; nt < 8; nt++)
                    mma_f16(acc[mt][nt], af[mt], bf[ks & 1][nt]);
        }
    }

    float2 bv[8];
    #pragma unroll
    for (int nt = 0; nt < 8; nt++)
        bv[nt] = *(const float2*)(bias + colBase + nb + nt * 8 + (lane & 3) * 2);

    #pragma unroll
    for (int mt = 0; mt < 2; mt++) {
        #pragma unroll
        for (int i = 0; i < 2; i++) {
            int row = rowBase + mb + mt * 16 + (lane >> 2) + i * 8;
            int dst = (EPI == 2) ? win_to_tok(row, shift) : row;
            #pragma unroll
            for (int nt = 0; nt < 8; nt++) {
                int col = colBase + nb + nt * 8 + (lane & 3) * 2;
                float v0 = acc[mt][nt][i * 2 + 0] + bv[nt].x;
                float v1 = acc[mt][nt][i * 2 + 1] + bv[nt].y;
                if (EPI == 0) {
                    *(unsigned*)((__half*)Cout + (size_t)row * N + col) = packh2(v0, v1);
                } else if (EPI == 1) {
                    v0 = 0.5f * v0 * (1.0f + erff(v0 * 0.70710678118654752f));
                    v1 = 0.5f * v1 * (1.0f + erff(v1 * 0.70710678118654752f));
                    *(unsigned*)((__half*)Cout + (size_t)row * N + col) = packh2(v0, v1);
                } else {
                    float2* rp = (float2*)(g_x + dst * 256 + col);
                    float2 r0 = *rp;
                    r0.x += v0; r0.y += v1;
                    *rp = r0;
                }
            }
        }
    }
}

// ---------------- final LN + [L,C] -> [C,L] transpose ----------------
__global__ __launch_bounds__(256) void k_final(const float* __restrict__ gam,
                                               const float* __restrict__ bet,
                                               float* __restrict__ out) {
    __shared__ float sm[256][33];
    int warp = threadIdx.x >> 5, lane = threadIdx.x & 31;
    int l0 = blockIdx.x << 5;
    float4 g0 = ((const float4*)gam)[lane*2], g1 = ((const float4*)gam)[lane*2+1];
    float4 b0 = ((const float4*)bet)[lane*2], b1 = ((const float4*)bet)[lane*2+1];
    #pragma unroll
    for (int i = 0; i < 4; i++) {
        int tok = (warp << 2) + i;
        const float4* xp = (const float4*)(g_x + (l0 + tok) * 256);
        float4 a = xp[lane*2], c = xp[lane*2+1];
        float s  = a.x + a.y + a.z + a.w + c.x + c.y + c.z + c.w;
        float sq = a.x*a.x + a.y*a.y + a.z*a.z + a.w*a.w
                 + c.x*c.x + c.y*c.y + c.z*c.z + c.w*c.w;
        #pragma unroll
        for (int o = 16; o; o >>= 1) {
            s  += __shfl_xor_sync(0xffffffffu, s, o);
            sq += __shfl_xor_sync(0xffffffffu, sq, o);
        }
        float mean = s * (1.0f / 256.0f);
        float inv = rsqrtf(sq * (1.0f / 256.0f) - mean * mean + 1e-5f);
        int cb = lane * 8;
        sm[cb+0][tok] = (a.x-mean)*inv*g0.x + b0.x;
        sm[cb+1][tok] = (a.y-mean)*inv*g0.y + b0.y;
        sm[cb+2][tok] = (a.z-mean)*inv*g0.z + b0.z;
        sm[cb+3][tok] = (a.w-mean)*inv*g0.w + b0.w;
        sm[cb+4][tok] = (c.x-mean)*inv*g1.x + b1.x;
        sm[cb+5][tok] = (c.y-mean)*inv*g1.y + b1.y;
        sm[cb+6][tok] = (c.z-mean)*inv*g1.z + b1.z;
        sm[cb+7][tok] = (c.w-mean)*inv*g1.w + b1.w;
    }
    __syncthreads();
    int lt = threadIdx.x & 31;
    int cw = threadIdx.x >> 5;
    #pragma unroll
    for (int cc = 0; cc < 32; cc++) {
        int c = (cc << 3) + cw;
        out[c * L_TOK + l0 + lt] = sm[c][lt];
    }
}

// ---------------- launch ----------------
#define GEMM_SMEM (3 * GSTG * 2)
extern "C" void kernel_launch(void* const* d_in, const int* in_sizes, int n_in,
                              void* d_out, int out_size) {
    const float* x      = (const float*)d_in[0];
    const float* norm_g = (const float*)d_in[4];
    const float* norm_b = (const float*)d_in[5];
    float* out = (float*)d_out;

    __half *p_win, *p_qkv, *p_att, *p_mlp, *p_w;
    cudaGetSymbolAddress((void**)&p_win, g_win);
    cudaGetSymbolAddress((void**)&p_qkv, g_qkv);
    cudaGetSymbolAddress((void**)&p_att, g_att);
    cudaGetSymbolAddress((void**)&p_mlp, g_mlp);
    cudaGetSymbolAddress((void**)&p_w,   g_wbuf);

    cudaFuncSetAttribute(k_gemm<0, __half>, cudaFuncAttributeMaxDynamicSharedMemorySize, GEMM_SMEM);
    cudaFuncSetAttribute(k_gemm<1, __half>, cudaFuncAttributeMaxDynamicSharedMemorySize, GEMM_SMEM);
    cudaFuncSetAttribute(k_gemm<2, float >, cudaFuncAttributeMaxDynamicSharedMemorySize, GEMM_SMEM);
    cudaFuncSetAttribute(k_gemm<3, float >, cudaFuncAttributeMaxDynamicSharedMemorySize, GEMM_SMEM);

    k_copy<<<8192, 256>>>(x);
    k_roundall<<<1536, 256>>>((const float*)d_in[8],  (const float*)d_in[11],
                              (const float*)d_in[15], (const float*)d_in[17],
                              (const float*)d_in[21], (const float*)d_in[24],
                              (const float*)d_in[28], (const float*)d_in[30]);

    for (int blk = 0; blk < 2; blk++) {
        int o = 6 + blk * 13;
        int shift = blk ? 2 : 0;
        const float* n1g   = (const float*)d_in[o+0];
        const float* n1b   = (const float*)d_in[o+1];
        const float* qkvb  = (const float*)d_in[o+3];
        const float* rpb   = (const float*)d_in[o+4];
        const float* projb = (const float*)d_in[o+6];
        const float* n2g   = (const float*)d_in[o+7];
        const float* n2b   = (const float*)d_in[o+8];
        const float* fc1b  = (const float*)d_in[o+10];
        const float* fc2b  = (const float*)d_in[o+12];
        __half* wbase = p_w + blk * 786432;

        k_ln<1><<<4096, 256>>>(n1g, n1b, shift);
        k_gemm<0, __half><<<dim3(6, 256), 256, GEMM_SMEM>>>(p_win, wbase,          qkvb,  p_qkv, 768, 256, 0);
        k_attn_tc<<<2048, 128>>>(rpb, shift);
        k_gemm<2, float ><<<dim3(2, 256), 256, GEMM_SMEM>>>(p_att, wbase + 196608, projb, (float*)nullptr, 256, 256, shift);
        k_ln<0><<<4096, 256>>>(n2g, n2b, 0);
        k_gemm<1, __half><<<dim3(8, 256), 256, GEMM_SMEM>>>(p_win, wbase + 262144, fc1b,  p_mlp, 1024, 256, 0);
        k_gemm<3, float ><<<dim3(2, 256), 256, GEMM_SMEM>>>(p_mlp, wbase + 524288, fc2b,  (float*)nullptr, 256, 1024, 0);
    }

    k_final<<<1024, 256>>>(norm_g, norm_b, out);
}